// round 2
// baseline (speedup 1.0000x reference)
#include <cuda_runtime.h>

// Problem constants (fixed shapes from reference)
#define BB   2
#define NN   16384
#define MM   4096
#define CC   64
#define KK   16
#define TILE 2048
#define WPB  8          // warps (queries) per block
#define NQ   (BB * MM)  // 8192 total queries

#define BIGF 1e30f

// Transposed features: (B, N, C). 8 MB scratch as __device__ global (no allocs allowed).
__device__ float g_xt[BB * NN * CC];

// ---------------------------------------------------------------------------
// Kernel 1: transpose x1 (B,C,N) -> g_xt (B,N,C) so neighbor gathers coalesce.
// ---------------------------------------------------------------------------
__global__ __launch_bounds__(256) void transpose_kernel(const float* __restrict__ x1) {
    __shared__ float t[32][33];
    const int b  = blockIdx.z;
    const int n0 = blockIdx.x * 32;
    const int c0 = blockIdx.y * 32;
    const int tx = threadIdx.x;   // 0..31
    const int ty = threadIdx.y;   // 0..7

    const float* src = x1  + (size_t)b * CC * NN;
    float*       dst = g_xt + (size_t)b * NN * CC;

#pragma unroll
    for (int i = 0; i < 32; i += 8)
        t[ty + i][tx] = src[(size_t)(c0 + ty + i) * NN + (n0 + tx)];
    __syncthreads();
#pragma unroll
    for (int i = 0; i < 32; i += 8)
        dst[(size_t)(n0 + ty + i) * CC + (c0 + tx)] = t[tx][ty + i];
}

// ---------------------------------------------------------------------------
// Kernel 2: per-warp exact KNN(16) + fused feature gather/mean.
// One warp handles one query. p1 is tiled through shared memory (SoA).
// Each lane keeps a private top-16 (registers, static-index predicated ops).
// Warp-shared pruning threshold tau = warp-min of lane worsts (provably safe:
// if d >= tau, the lane achieving tau already holds 16 elements <= d, so d
// cannot be in the global top-16).
// ---------------------------------------------------------------------------
__global__ __launch_bounds__(32 * WPB) void knn_kernel(const float* __restrict__ p1,
                                                       const float* __restrict__ p2,
                                                       float* __restrict__ out) {
    __shared__ float sx[TILE];
    __shared__ float sy[TILE];
    __shared__ float sz[TILE];

    const int warp = threadIdx.x >> 5;
    const int lane = threadIdx.x & 31;
    const int q    = blockIdx.x * WPB + warp;    // 0..NQ-1
    const int b    = q >> 12;                    // q / MM  (MM = 4096)
    const int m    = q & (MM - 1);

    const float* p1b = p1 + (size_t)b * NN * 3;
    const float qx = p2[((size_t)b * MM + m) * 3 + 0];
    const float qy = p2[((size_t)b * MM + m) * 3 + 1];
    const float qz = p2[((size_t)b * MM + m) * 3 + 2];

    float bd[KK];
    int   bi[KK];
#pragma unroll
    for (int k = 0; k < KK; k++) { bd[k] = BIGF; bi[k] = 0; }
    float worst    = BIGF;   // max of my 16
    int   worstpos = 0;
    float thr      = BIGF;   // min(my worst, warp tau) — safe insert gate

    for (int t0 = 0; t0 < NN; t0 += TILE) {
        __syncthreads();
        // Cooperative tile load (p1 is small; stays L2-resident)
        for (int i = threadIdx.x; i < TILE; i += 32 * WPB) {
            const int pi = (t0 + i) * 3;
            sx[i] = p1b[pi + 0];
            sy[i] = p1b[pi + 1];
            sz[i] = p1b[pi + 2];
        }
        __syncthreads();

        for (int jc = 0; jc < TILE; jc += 16 * 32) {
#pragma unroll 1
            for (int j = 0; j < 16; j++) {
                const int t = jc + j * 32 + lane;
                const float dx = qx - sx[t];
                const float dy = qy - sy[t];
                const float dz = qz - sz[t];
                const float d  = fmaf(dx, dx, fmaf(dy, dy, dz * dz));
                if (d < thr) {
                    // replace current worst (static-index predicated writes)
#pragma unroll
                    for (int k = 0; k < KK; k++)
                        if (k == worstpos) { bd[k] = d; bi[k] = t0 + t; }
                    // rescan for new worst
                    worst = bd[0]; worstpos = 0;
#pragma unroll
                    for (int k = 1; k < KK; k++)
                        if (bd[k] > worst) { worst = bd[k]; worstpos = k; }
                    thr = fminf(thr, worst);
                }
            }
            // refresh tau: warp-min of lane worsts
            float tau = worst;
#pragma unroll
            for (int off = 16; off; off >>= 1)
                tau = fminf(tau, __shfl_xor_sync(0xffffffffu, tau, off));
            thr = tau;   // tau <= own worst always
        }
    }

    // --- per-lane bitonic sort (ascending), all indices compile-time ---
#pragma unroll
    for (int sz = 2; sz <= KK; sz <<= 1) {
#pragma unroll
        for (int st = sz >> 1; st > 0; st >>= 1) {
#pragma unroll
            for (int i = 0; i < KK; i++) {
                const int jj = i ^ st;
                if (jj > i) {
                    const bool up = ((i & sz) == 0);
                    const bool sw = (bd[i] > bd[jj]) == up;
                    const float td = sw ? bd[jj] : bd[i];
                    const float td2 = sw ? bd[i] : bd[jj];
                    const int   ti = sw ? bi[jj] : bi[i];
                    const int   ti2 = sw ? bi[i] : bi[jj];
                    bd[i] = td; bd[jj] = td2;
                    bi[i] = ti; bi[jj] = ti2;
                }
            }
        }
    }

    // --- 16-round k-way merge across lanes, fused with feature gather ---
    const float* ft = g_xt + (size_t)b * NN * CC;
    int   p  = 0;
    float a0 = 0.0f, a1 = 0.0f;
#pragma unroll 1
    for (int r = 0; r < KK; r++) {
        float hv = BIGF; int hi = 0;
#pragma unroll
        for (int k = 0; k < KK; k++)
            if (k == p) { hv = bd[k]; hi = bi[k]; }
        // warp argmin of (hv, lane) — lexicographic, deterministic
        float v  = hv;
        int   ln = lane;
#pragma unroll
        for (int off = 16; off; off >>= 1) {
            const float ov = __shfl_xor_sync(0xffffffffu, v, off);
            const int   ol = __shfl_xor_sync(0xffffffffu, ln, off);
            if (ov < v || (ov == v && ol < ln)) { v = ov; ln = ol; }
        }
        const int gidx = __shfl_sync(0xffffffffu, hi, ln);
        p += (lane == ln) ? 1 : 0;
        // gather: lane <-> channel, coalesced 2x128B per neighbor
        const float* f = ft + (size_t)gidx * CC;
        a0 += f[lane];
        a1 += f[lane + 32];
    }

    out[((size_t)b * CC + lane) * MM + m]        = a0 * (1.0f / KK);
    out[((size_t)b * CC + lane + 32) * MM + m]   = a1 * (1.0f / KK);
}

// ---------------------------------------------------------------------------
extern "C" void kernel_launch(void* const* d_in, const int* in_sizes, int n_in,
                              void* d_out, int out_size) {
    const float* p1 = (const float*)d_in[0];   // (B, N, 3)
    const float* x1 = (const float*)d_in[1];   // (B, C, N)
    const float* p2 = (const float*)d_in[2];   // (B, M, 3)
    float* out = (float*)d_out;                // (B, C, M)

    dim3 tb(32, 8);
    dim3 tg(NN / 32, CC / 32, BB);
    transpose_kernel<<<tg, tb>>>(x1);

    knn_kernel<<<NQ / WPB, 32 * WPB>>>(p1, p2, out);
}